// round 4
// baseline (speedup 1.0000x reference)
#include <cuda_runtime.h>
#include <cstddef>

#define NMAX 100000
#define EMAX 1600000
#define F    128      // feature dim
#define K2   256      // concat dim
#define NT   64       // nodes per fused block
#define NPAIR 32      // NT/2 node pairs per block
#define SCAN_CHUNK 1024
#define NBLK_SCAN  ((NMAX + SCAN_CHUNK - 1) / SCAN_CHUNK)   // 98

// ---------------- scratch ----------------------------------------------------
__device__ int   g_cnt[NMAX];
__device__ int   g_off[NMAX];
__device__ int   g_cur[NMAX];
__device__ int   g_csr[EMAX];
__device__ float g_Wt[K2 * F];        // Wt[k][j] = W[j][k]  (128 KB)
__device__ int   g_bsum[NBLK_SCAN];
__device__ int   g_bbase[NBLK_SCAN];

// ---------------- f32x2 helpers ----------------------------------------------
__device__ __forceinline__ unsigned long long fma2(unsigned long long a,
                                                   unsigned long long b,
                                                   unsigned long long c) {
    unsigned long long d;
    asm("fma.rn.f32x2 %0, %1, %2, %3;" : "=l"(d) : "l"(a), "l"(b), "l"(c));
    return d;
}
__device__ __forceinline__ unsigned long long pack2(float x, float y) {
    unsigned long long r;
    asm("mov.b64 %0, {%1, %2};" : "=l"(r) : "f"(x), "f"(y));
    return r;
}
__device__ __forceinline__ float2 unpack2(unsigned long long v) {
    float2 r;
    asm("mov.b64 {%0, %1}, %2;" : "=f"(r.x), "=f"(r.y) : "l"(v));
    return r;
}

// ---------------- kernel: transpose W ------------------------------------------
__global__ void transpose_w(const float* __restrict__ W) {
    int k = blockIdx.x;     // 0..255
    int j = threadIdx.x;    // 0..127
    g_Wt[k * F + j] = W[j * K2 + k];
}

// ---------------- kernel: degree histogram -------------------------------------
__global__ void hist_dst(const int* __restrict__ dst, int E) {
    int i = blockIdx.x * blockDim.x + threadIdx.x;
    if (i < E) atomicAdd(&g_cnt[dst[i]], 1);
}

// ---------------- parallel exclusive scan (3 kernels) ---------------------------
__global__ void scan_part1(int N) {
    const int b = blockIdx.x, tid = threadIdx.x;
    int i0 = b * SCAN_CHUNK + tid * 4;
    int s = 0;
    #pragma unroll
    for (int q = 0; q < 4; q++) { int i = i0 + q; if (i < N) s += g_cnt[i]; }
    #pragma unroll
    for (int o = 16; o > 0; o >>= 1) s += __shfl_xor_sync(0xffffffffu, s, o);
    __shared__ int ws[8];
    if ((tid & 31) == 0) ws[tid >> 5] = s;
    __syncthreads();
    if (tid == 0) {
        int t = 0;
        #pragma unroll
        for (int w = 0; w < 8; w++) t += ws[w];
        g_bsum[b] = t;
    }
}
__global__ void scan_part2(int nb) {
    const int tid = threadIdx.x, lane = tid & 31, wid = tid >> 5;
    int x = (tid < nb) ? g_bsum[tid] : 0;
    int inc = x;
    #pragma unroll
    for (int o = 1; o < 32; o <<= 1) {
        int t = __shfl_up_sync(0xffffffffu, inc, o);
        if (lane >= o) inc += t;
    }
    __shared__ int ws[4];
    if (lane == 31) ws[wid] = inc;
    __syncthreads();
    int wbase = 0;
    for (int w = 0; w < wid; w++) wbase += ws[w];
    if (tid < nb) g_bbase[tid] = wbase + inc - x;
}
__global__ void scan_part3(int N) {
    const int b = blockIdx.x, tid = threadIdx.x;
    const int lane = tid & 31, wid = tid >> 5;
    int i0 = b * SCAN_CHUNK + tid * 4;
    int v[4];
    #pragma unroll
    for (int q = 0; q < 4; q++) { int i = i0 + q; v[q] = (i < N) ? g_cnt[i] : 0; }
    int s = v[0] + v[1] + v[2] + v[3];
    int inc = s;
    #pragma unroll
    for (int o = 1; o < 32; o <<= 1) {
        int t = __shfl_up_sync(0xffffffffu, inc, o);
        if (lane >= o) inc += t;
    }
    __shared__ int ws[8], wse[8];
    if (lane == 31) ws[wid] = inc;
    __syncthreads();
    if (tid == 0) {
        int r = 0;
        #pragma unroll
        for (int w = 0; w < 8; w++) { wse[w] = r; r += ws[w]; }
    }
    __syncthreads();
    int run = g_bbase[b] + wse[wid] + (inc - s);
    #pragma unroll
    for (int q = 0; q < 4; q++) {
        int i = i0 + q;
        if (i < N) { g_off[i] = run; g_cur[i] = run; }
        run += v[q];
    }
}

// ---------------- kernel: CSR fill ----------------------------------------------
__global__ void fill_csr(const int* __restrict__ src,
                         const int* __restrict__ dst, int E) {
    int i = blockIdx.x * blockDim.x + threadIdx.x;
    if (i < E) {
        int pos = atomicAdd(&g_cur[dst[i]], 1);
        g_csr[pos] = src[i];
    }
}

// ---------------- LN + affine + ReLU + store helper ------------------------------
__device__ __forceinline__ void ln_store(float z0, float z1, float z2, float z3,
                                         const float4 gg, const float4 be,
                                         bool valid, float* ptr) {
    float s = z0 + z1 + z2 + z3;
    #pragma unroll
    for (int o = 16; o > 0; o >>= 1) s += __shfl_xor_sync(0xffffffffu, s, o);
    const float mu = s * (1.0f / 128.0f);
    float d0 = z0 - mu, d1 = z1 - mu, d2 = z2 - mu, d3 = z3 - mu;
    float q = d0 * d0 + d1 * d1 + d2 * d2 + d3 * d3;
    #pragma unroll
    for (int o = 16; o > 0; o >>= 1) q += __shfl_xor_sync(0xffffffffu, q, o);
    const float inv = rsqrtf(q * (1.0f / 128.0f) + 1e-5f);
    if (valid) {
        float4 r;
        r.x = fmaxf(d0 * inv * gg.x + be.x, 0.0f);
        r.y = fmaxf(d1 * inv * gg.y + be.y, 0.0f);
        r.z = fmaxf(d2 * inv * gg.z + be.z, 0.0f);
        r.w = fmaxf(d3 * inv * gg.w + be.w, 0.0f);
        *reinterpret_cast<float4*>(ptr) = r;
    }
}

// ---------------- fused: gather-mean + concat-GEMM(f32x2) + LN + ReLU ------------
// 64 threads = 2 warps. Warp w owns 32 nodes = 16 pairs (p0 = 16w).
// Lane owns output cols j0=4*lane..j0+3 (full row per warp -> LN via shfl).
// Shared x layout: xk[pair][k] as u64 node-pair pack (x[2p][k], x[2p+1][k]).
__global__ __launch_bounds__(64, 3)
void fused_node(const float* __restrict__ h,
                const float* __restrict__ bias,
                const float* __restrict__ gamma,
                const float* __restrict__ beta,
                float* __restrict__ out,
                int N) {
    extern __shared__ unsigned long long xk[];   // [NPAIR][K2] u64 = 65536 B
    const int tid   = threadIdx.x;
    const int lane  = tid & 31;
    const int warp  = tid >> 5;                  // 0 or 1
    const int node0 = blockIdx.x * NT;
    const int nval  = min(NT, N - node0);
    const int j0    = lane * 4;
    const int p0    = warp * 16;

    float* xf = reinterpret_cast<float*>(xk);    // float view

    // ---- stage h half (k in [0,128)) ----
    #pragma unroll
    for (int idx = tid; idx < NT * (F / 4); idx += 64) {
        int n = idx >> 5;            // node 0..63
        int c = idx & 31;            // float4 index
        float4 v = make_float4(0.f, 0.f, 0.f, 0.f);
        if (n < nval)
            v = *reinterpret_cast<const float4*>(h + (size_t)(node0 + n) * F + c * 4);
        int half = n & 1, pair = n >> 1;
        float* b = xf + ((size_t)pair * K2) * 2 + half;
        b[(c * 4 + 0) * 2] = v.x;
        b[(c * 4 + 1) * 2] = v.y;
        b[(c * 4 + 2) * 2] = v.z;
        b[(c * 4 + 3) * 2] = v.w;
    }

    // ---- gather-mean half (k in [128,256)): warp gathers its 32 nodes ----
    for (int nn = warp * 32; nn < warp * 32 + 32; nn++) {
        float4 a = make_float4(0.f, 0.f, 0.f, 0.f);
        if (nn < nval) {
            const int gn  = node0 + nn;
            const int beg = g_off[gn];
            const int cnt = g_cnt[gn];
            int t = 0;
            for (; t + 4 <= cnt; t += 4) {
                int s0 = __ldg(g_csr + beg + t);
                int s1 = __ldg(g_csr + beg + t + 1);
                int s2 = __ldg(g_csr + beg + t + 2);
                int s3 = __ldg(g_csr + beg + t + 3);
                float4 v0 = *reinterpret_cast<const float4*>(h + (size_t)s0 * F + j0);
                float4 v1 = *reinterpret_cast<const float4*>(h + (size_t)s1 * F + j0);
                float4 v2 = *reinterpret_cast<const float4*>(h + (size_t)s2 * F + j0);
                float4 v3 = *reinterpret_cast<const float4*>(h + (size_t)s3 * F + j0);
                a.x += (v0.x + v1.x) + (v2.x + v3.x);
                a.y += (v0.y + v1.y) + (v2.y + v3.y);
                a.z += (v0.z + v1.z) + (v2.z + v3.z);
                a.w += (v0.w + v1.w) + (v2.w + v3.w);
            }
            for (; t < cnt; t++) {
                int s0 = __ldg(g_csr + beg + t);
                float4 v0 = *reinterpret_cast<const float4*>(h + (size_t)s0 * F + j0);
                a.x += v0.x; a.y += v0.y; a.z += v0.z; a.w += v0.w;
            }
            float r = 1.0f / fmaxf((float)cnt, 1.0f);
            a.x *= r; a.y *= r; a.z *= r; a.w *= r;
        }
        int half = nn & 1, pair = nn >> 1;
        float* b = xf + ((size_t)pair * K2) * 2 + half;
        b[(F + j0 + 0) * 2] = a.x;
        b[(F + j0 + 1) * 2] = a.y;
        b[(F + j0 + 2) * 2] = a.z;
        b[(F + j0 + 3) * 2] = a.w;
    }
    __syncthreads();

    // ---- GEMM: 32 nodes (16 pairs) x 4 cols per thread, f32x2 over pairs ----
    unsigned long long acc[16][4];
    #pragma unroll
    for (int i = 0; i < 16; i++)
        #pragma unroll
        for (int c = 0; c < 4; c++) acc[i][c] = 0ull;

    const float* wrow = g_Wt + j0;
    float4 wA = __ldg(reinterpret_cast<const float4*>(wrow));
    float4 wB = __ldg(reinterpret_cast<const float4*>(wrow + F));

    #pragma unroll 1
    for (int k = 0; k < K2; k += 2) {
        // prefetch next weight rows (1-deep pipeline over the ~256cyc body)
        float4 nA, nB;
        if (k + 2 < K2) {
            nA = __ldg(reinterpret_cast<const float4*>(wrow + (size_t)(k + 2) * F));
            nB = __ldg(reinterpret_cast<const float4*>(wrow + (size_t)(k + 3) * F));
        }
        const unsigned long long wa0 = pack2(wA.x, wA.x);
        const unsigned long long wa1 = pack2(wA.y, wA.y);
        const unsigned long long wa2 = pack2(wA.z, wA.z);
        const unsigned long long wa3 = pack2(wA.w, wA.w);
        const unsigned long long wb0 = pack2(wB.x, wB.x);
        const unsigned long long wb1 = pack2(wB.y, wB.y);
        const unsigned long long wb2 = pack2(wB.z, wB.z);
        const unsigned long long wb3 = pack2(wB.w, wB.w);
        #pragma unroll
        for (int i = 0; i < 16; i++) {
            // one LDS.128 broadcast: pair value at k and k+1
            const ulonglong2 xv = *reinterpret_cast<const ulonglong2*>(
                xk + ((size_t)(p0 + i) * K2 + k));
            acc[i][0] = fma2(xv.x, wa0, acc[i][0]);
            acc[i][1] = fma2(xv.x, wa1, acc[i][1]);
            acc[i][2] = fma2(xv.x, wa2, acc[i][2]);
            acc[i][3] = fma2(xv.x, wa3, acc[i][3]);
            acc[i][0] = fma2(xv.y, wb0, acc[i][0]);
            acc[i][1] = fma2(xv.y, wb1, acc[i][1]);
            acc[i][2] = fma2(xv.y, wb2, acc[i][2]);
            acc[i][3] = fma2(xv.y, wb3, acc[i][3]);
        }
        wA = nA; wB = nB;
    }

    // ---- epilogue ----
    const float4 bb = *reinterpret_cast<const float4*>(bias  + j0);
    const float4 gg = *reinterpret_cast<const float4*>(gamma + j0);
    const float4 be = *reinterpret_cast<const float4*>(beta  + j0);

    #pragma unroll
    for (int i = 0; i < 16; i++) {
        float2 u0 = unpack2(acc[i][0]);
        float2 u1 = unpack2(acc[i][1]);
        float2 u2 = unpack2(acc[i][2]);
        float2 u3 = unpack2(acc[i][3]);
        int nn = 2 * (p0 + i);                 // even node of the pair
        ln_store(u0.x + bb.x, u1.x + bb.y, u2.x + bb.z, u3.x + bb.w,
                 gg, be, nn < nval,
                 out + (size_t)(node0 + nn) * F + j0);
        ln_store(u0.y + bb.x, u1.y + bb.y, u2.y + bb.z, u3.y + bb.w,
                 gg, be, nn + 1 < nval,
                 out + (size_t)(node0 + nn + 1) * F + j0);
    }
}

// ---------------- launch ---------------------------------------------------------
extern "C" void kernel_launch(void* const* d_in, const int* in_sizes, int n_in,
                              void* d_out, int out_size) {
    const float* h     = (const float*)d_in[0];
    const int*   src   = (const int*)  d_in[1];
    const int*   dst   = (const int*)  d_in[2];
    const float* W     = (const float*)d_in[3];
    const float* bias  = (const float*)d_in[4];
    const float* gamma = (const float*)d_in[5];
    const float* beta  = (const float*)d_in[6];
    float* out = (float*)d_out;

    const int N = in_sizes[0] / F;
    const int E = in_sizes[1];

    void* cnt_ptr = nullptr;
    cudaGetSymbolAddress(&cnt_ptr, g_cnt);
    cudaMemsetAsync(cnt_ptr, 0, (size_t)N * sizeof(int));

    transpose_w<<<K2, F>>>(W);
    hist_dst<<<(E + 255) / 256, 256>>>(dst, E);

    int nb = (N + SCAN_CHUNK - 1) / SCAN_CHUNK;
    scan_part1<<<nb, 256>>>(N);
    scan_part2<<<1, 128>>>(nb);
    scan_part3<<<nb, 256>>>(N);

    fill_csr<<<(E + 255) / 256, 256>>>(src, dst, E);

    static int smem_set = 0;
    const int smem_bytes = NPAIR * K2 * sizeof(unsigned long long);  // 65536
    if (!smem_set) {
        cudaFuncSetAttribute(fused_node, cudaFuncAttributeMaxDynamicSharedMemorySize,
                             smem_bytes);
        smem_set = 1;
    }
    int blocks_n = (N + NT - 1) / NT;
    fused_node<<<blocks_n, 64, smem_bytes>>>(h, bias, gamma, beta, out, N);
}

// round 7
// speedup vs baseline: 1.3739x; 1.3739x over previous
#include <cuda_runtime.h>
#include <cuda_bf16.h>
#include <cstdint>
#include <cstddef>

#define NMAX 100000
#define EMAX 1600000
#define F    128
#define K2   256
#define MT   128            // nodes per GEMM tile
#define SCAN_CHUNK 1024
#define NBLK_SCAN  ((NMAX + SCAN_CHUNK - 1) / SCAN_CHUNK)

// x smem: [128 rows][264 bf16]  (528 B/row)
#define XSTR 264
// W smem: [128 cols][136 bf16]  (272 B/row)
#define WSTR 136

// smem byte offsets
#define S_BIAS 0
#define S_GAM  512
#define S_BET  1024
#define S_XH   2048
#define S_XL   (S_XH + 128 * XSTR * 2)          // 69632
#define S_WH   (S_XL + 128 * XSTR * 2)          // 137216
#define S_WL   (S_WH + 128 * WSTR * 2)          // 172032
#define S_END  (S_WL + 128 * WSTR * 2)          // 206848

// ---------------- scratch ------------------------------------------------------
__device__ int g_cnt[NMAX];
__device__ int g_off[NMAX];
__device__ int g_cur[NMAX];
__device__ int g_csr[EMAX];
__device__ unsigned long long g_wh[128 * 64];   // bf16 hi [col][256] as u64x64
__device__ unsigned long long g_wl[128 * 64];   // bf16 lo
__device__ int g_bsum[NBLK_SCAN];
__device__ int g_bbase[NBLK_SCAN];

// ---------------- helpers ------------------------------------------------------
__device__ __forceinline__ uint32_t smem_u32(const void* p) {
    uint32_t a;
    asm("{ .reg .u64 t; cvta.to.shared.u64 t, %1; cvt.u32.u64 %0, t; }" : "=r"(a) : "l"(p));
    return a;
}
__device__ __forceinline__ unsigned long long pk4(__nv_bfloat16 a, __nv_bfloat16 b,
                                                  __nv_bfloat16 c, __nv_bfloat16 d) {
    unsigned short u0 = __bfloat16_as_ushort(a), u1 = __bfloat16_as_ushort(b);
    unsigned short u2 = __bfloat16_as_ushort(c), u3 = __bfloat16_as_ushort(d);
    return (unsigned long long)u0 | ((unsigned long long)u1 << 16)
         | ((unsigned long long)u2 << 32) | ((unsigned long long)u3 << 48);
}
__device__ __forceinline__ void split4(float4 v, unsigned long long& hi,
                                       unsigned long long& lo) {
    __nv_bfloat16 hx = __float2bfloat16_rn(v.x), hy = __float2bfloat16_rn(v.y);
    __nv_bfloat16 hz = __float2bfloat16_rn(v.z), hw = __float2bfloat16_rn(v.w);
    __nv_bfloat16 lx = __float2bfloat16_rn(v.x - __bfloat162float(hx));
    __nv_bfloat16 ly = __float2bfloat16_rn(v.y - __bfloat162float(hy));
    __nv_bfloat16 lz = __float2bfloat16_rn(v.z - __bfloat162float(hz));
    __nv_bfloat16 lw = __float2bfloat16_rn(v.w - __bfloat162float(hw));
    hi = pk4(hx, hy, hz, hw);
    lo = pk4(lx, ly, lz, lw);
}
__device__ __forceinline__ void ldsm_x4(uint32_t* r, uint32_t addr) {
    asm volatile("ldmatrix.sync.aligned.m8n8.x4.shared.b16 {%0,%1,%2,%3}, [%4];"
                 : "=r"(r[0]), "=r"(r[1]), "=r"(r[2]), "=r"(r[3]) : "r"(addr));
}
// B operand: W stored n-major [n][k]; plain (non-trans) ldmatrix gives
// thread -> (n = lane/4, k = 2*(lane%4)+{0,1}) which IS the mma B fragment.
__device__ __forceinline__ void ldsm_x2(uint32_t* r, uint32_t addr) {
    asm volatile("ldmatrix.sync.aligned.m8n8.x2.shared.b16 {%0,%1}, [%2];"
                 : "=r"(r[0]), "=r"(r[1]) : "r"(addr));
}
__device__ __forceinline__ void mma_bf16(float* d, const uint32_t* a, const uint32_t* b) {
    asm volatile("mma.sync.aligned.m16n8k16.row.col.f32.bf16.bf16.f32 "
                 "{%0,%1,%2,%3}, {%4,%5,%6,%7}, {%8,%9}, {%0,%1,%2,%3};"
                 : "+f"(d[0]), "+f"(d[1]), "+f"(d[2]), "+f"(d[3])
                 : "r"(a[0]), "r"(a[1]), "r"(a[2]), "r"(a[3]), "r"(b[0]), "r"(b[1]));
}

// ---------------- prep: split W into bf16 hi/lo [col][256] -----------------------
__global__ void wsplit(const float* __restrict__ W) {
    int j  = blockIdx.x;          // output col 0..127
    int f4 = threadIdx.x;         // 0..63  (k group of 4)
    float4 v = *reinterpret_cast<const float4*>(W + (size_t)j * K2 + f4 * 4);
    unsigned long long hi, lo;
    split4(v, hi, lo);
    g_wh[j * 64 + f4] = hi;
    g_wl[j * 64 + f4] = lo;
}

// ---------------- prep: histogram / scan / fill ----------------------------------
__global__ void hist_dst(const int* __restrict__ dst, int E) {
    int i = blockIdx.x * blockDim.x + threadIdx.x;
    if (i < E) atomicAdd(&g_cnt[dst[i]], 1);
}
__global__ void scan_part1(int N) {
    const int b = blockIdx.x, tid = threadIdx.x;
    int i0 = b * SCAN_CHUNK + tid * 4;
    int s = 0;
    #pragma unroll
    for (int q = 0; q < 4; q++) { int i = i0 + q; if (i < N) s += g_cnt[i]; }
    #pragma unroll
    for (int o = 16; o > 0; o >>= 1) s += __shfl_xor_sync(0xffffffffu, s, o);
    __shared__ int ws[8];
    if ((tid & 31) == 0) ws[tid >> 5] = s;
    __syncthreads();
    if (tid == 0) {
        int t = 0;
        #pragma unroll
        for (int w = 0; w < 8; w++) t += ws[w];
        g_bsum[b] = t;
    }
}
__global__ void scan_part2(int nb) {
    const int tid = threadIdx.x, lane = tid & 31, wid = tid >> 5;
    int x = (tid < nb) ? g_bsum[tid] : 0;
    int inc = x;
    #pragma unroll
    for (int o = 1; o < 32; o <<= 1) {
        int t = __shfl_up_sync(0xffffffffu, inc, o);
        if (lane >= o) inc += t;
    }
    __shared__ int ws[4];
    if (lane == 31) ws[wid] = inc;
    __syncthreads();
    int wbase = 0;
    for (int w = 0; w < wid; w++) wbase += ws[w];
    if (tid < nb) g_bbase[tid] = wbase + inc - x;
}
__global__ void scan_part3(int N) {
    const int b = blockIdx.x, tid = threadIdx.x;
    const int lane = tid & 31, wid = tid >> 5;
    int i0 = b * SCAN_CHUNK + tid * 4;
    int v[4];
    #pragma unroll
    for (int q = 0; q < 4; q++) { int i = i0 + q; v[q] = (i < N) ? g_cnt[i] : 0; }
    int s = v[0] + v[1] + v[2] + v[3];
    int inc = s;
    #pragma unroll
    for (int o = 1; o < 32; o <<= 1) {
        int t = __shfl_up_sync(0xffffffffu, inc, o);
        if (lane >= o) inc += t;
    }
    __shared__ int ws[8], wse[8];
    if (lane == 31) ws[wid] = inc;
    __syncthreads();
    if (tid == 0) {
        int r = 0;
        #pragma unroll
        for (int w = 0; w < 8; w++) { wse[w] = r; r += ws[w]; }
    }
    __syncthreads();
    int run = g_bbase[b] + wse[wid] + (inc - s);
    #pragma unroll
    for (int q = 0; q < 4; q++) {
        int i = i0 + q;
        if (i < N) { g_off[i] = run; g_cur[i] = run; }
        run += v[q];
    }
}
__global__ void fill_csr(const int* __restrict__ src,
                         const int* __restrict__ dst, int E) {
    int i = blockIdx.x * blockDim.x + threadIdx.x;
    if (i < E) {
        int pos = atomicAdd(&g_cur[dst[i]], 1);
        g_csr[pos] = src[i];
    }
}

// ---------------- fused: gather + mma.sync GEMM + LN + ReLU ----------------------
__global__ __launch_bounds__(256, 1)
void fused_gemm(const float* __restrict__ h,
                const float* __restrict__ bias,
                const float* __restrict__ gamma,
                const float* __restrict__ beta,
                float* __restrict__ out,
                int N) {
    extern __shared__ char smem[];
    const uint32_t sb  = smem_u32(smem);
    const int tid  = threadIdx.x;
    const int lane = tid & 31;
    const int warp = tid >> 5;            // 0..7; warp owns rows m0..m0+15
    const int m0   = warp * 16;
    const int tile0 = blockIdx.x * MT;
    const int nval  = min(MT, N - tile0);

    // params
    if (tid < F) {
        *reinterpret_cast<float*>(smem + S_BIAS + tid * 4) = bias[tid];
        *reinterpret_cast<float*>(smem + S_GAM  + tid * 4) = gamma[tid];
        *reinterpret_cast<float*>(smem + S_BET  + tid * 4) = beta[tid];
    }

    // ---- stage W chunk 0 ----
    {
        const uint4* whs = reinterpret_cast<const uint4*>(g_wh);
        const uint4* wls = reinterpret_cast<const uint4*>(g_wl);
        #pragma unroll
        for (int it = 0; it < 8; it++) {
            int i = it * 256 + tid;        // 2048
            int col = i >> 4, q = i & 15;
            *reinterpret_cast<uint4*>(smem + S_WH + col * (WSTR * 2) + q * 16)
                = whs[col * 32 + q];
            *reinterpret_cast<uint4*>(smem + S_WL + col * (WSTR * 2) + q * 16)
                = wls[col * 32 + q];
        }
    }

    // ---- stage x (k 0..127) from h, bf16 split ----
    #pragma unroll
    for (int it = 0; it < 16; it++) {
        int idx = it * 256 + tid;          // 4096 float4 slots
        int row = idx >> 5;
        int c   = idx & 31;                // float4 idx -> k0 = 4c
        float4 v = make_float4(0.f, 0.f, 0.f, 0.f);
        if (row < nval)
            v = *reinterpret_cast<const float4*>(h + (size_t)(tile0 + row) * F + c * 4);
        unsigned long long hi, lo;
        split4(v, hi, lo);
        *reinterpret_cast<unsigned long long*>(smem + S_XH + row * (XSTR * 2) + c * 8) = hi;
        *reinterpret_cast<unsigned long long*>(smem + S_XL + row * (XSTR * 2) + c * 8) = lo;
    }

    // ---- gather-mean (k 128..255): warp per node, lane per 4 cols ----
    const int j0 = lane * 4;
    for (int i = 0; i < 16; i++) {
        const int nn = warp * 16 + i;
        float4 a = make_float4(0.f, 0.f, 0.f, 0.f);
        if (nn < nval) {
            const int gn  = tile0 + nn;
            const int beg = g_off[gn];
            const int cnt = g_cnt[gn];
            int t = 0;
            for (; t + 4 <= cnt; t += 4) {
                int s0 = __ldg(g_csr + beg + t);
                int s1 = __ldg(g_csr + beg + t + 1);
                int s2 = __ldg(g_csr + beg + t + 2);
                int s3 = __ldg(g_csr + beg + t + 3);
                float4 v0 = *reinterpret_cast<const float4*>(h + (size_t)s0 * F + j0);
                float4 v1 = *reinterpret_cast<const float4*>(h + (size_t)s1 * F + j0);
                float4 v2 = *reinterpret_cast<const float4*>(h + (size_t)s2 * F + j0);
                float4 v3 = *reinterpret_cast<const float4*>(h + (size_t)s3 * F + j0);
                a.x += (v0.x + v1.x) + (v2.x + v3.x);
                a.y += (v0.y + v1.y) + (v2.y + v3.y);
                a.z += (v0.z + v1.z) + (v2.z + v3.z);
                a.w += (v0.w + v1.w) + (v2.w + v3.w);
            }
            for (; t < cnt; t++) {
                int s0 = __ldg(g_csr + beg + t);
                float4 v0 = *reinterpret_cast<const float4*>(h + (size_t)s0 * F + j0);
                a.x += v0.x; a.y += v0.y; a.z += v0.z; a.w += v0.w;
            }
            float r = 1.0f / fmaxf((float)cnt, 1.0f);
            a.x *= r; a.y *= r; a.z *= r; a.w *= r;
        }
        unsigned long long hi, lo;
        split4(a, hi, lo);
        *reinterpret_cast<unsigned long long*>(
            smem + S_XH + nn * (XSTR * 2) + (F + j0) * 2) = hi;
        *reinterpret_cast<unsigned long long*>(
            smem + S_XL + nn * (XSTR * 2) + (F + j0) * 2) = lo;
    }
    __syncthreads();

    // ---- GEMM via mma.sync, 3-term bf16 split, fp32 accum ----
    float acc[16][4];
    #pragma unroll
    for (int t = 0; t < 16; t++)
        #pragma unroll
        for (int c = 0; c < 4; c++) acc[t][c] = 0.f;

    // per-lane ldmatrix address components
    const int agrp = lane >> 3, ar = lane & 7;
    const int arow = m0 + ar + ((agrp & 1) ? 8 : 0);
    const int akof = (agrp & 2) ? 8 : 0;
    const uint32_t a_off = (uint32_t)arow * (XSTR * 2) + akof * 2;
    const int l15 = lane & 15;
    const uint32_t b_off = (uint32_t)(l15 & 7) * (WSTR * 2) + ((l15 >> 3) ? 16 : 0);

    #pragma unroll
    for (int ch = 0; ch < 2; ch++) {
        if (ch == 1) {
            __syncthreads();   // all warps done reading W chunk 0
            const uint4* whs = reinterpret_cast<const uint4*>(g_wh);
            const uint4* wls = reinterpret_cast<const uint4*>(g_wl);
            #pragma unroll
            for (int it = 0; it < 8; it++) {
                int i = it * 256 + tid;
                int col = i >> 4, q = i & 15;
                *reinterpret_cast<uint4*>(smem + S_WH + col * (WSTR * 2) + q * 16)
                    = whs[col * 32 + 16 + q];
                *reinterpret_cast<uint4*>(smem + S_WL + col * (WSTR * 2) + q * 16)
                    = wls[col * 32 + 16 + q];
            }
            __syncthreads();
        }
        #pragma unroll
        for (int s = 0; s < 8; s++) {
            const uint32_t kg = ch * 128 + s * 16;
            uint32_t ah[4], al[4];
            ldsm_x4(ah, sb + S_XH + a_off + kg * 2);
            ldsm_x4(al, sb + S_XL + a_off + kg * 2);
            #pragma unroll
            for (int t = 0; t < 16; t++) {
                const uint32_t bo = (uint32_t)t * 8 * (WSTR * 2) + b_off + s * 32;
                uint32_t bh[2], bl[2];
                ldsm_x2(bh, sb + S_WH + bo);
                mma_bf16(acc[t], ah, bh);
                mma_bf16(acc[t], al, bh);
                ldsm_x2(bl, sb + S_WL + bo);
                mma_bf16(acc[t], ah, bl);
            }
        }
    }

    // ---- epilogue: bias + LN (quad reduction) + affine + ReLU + store ----
    const int quad = lane >> 2;      // row within 8
    const int qid  = lane & 3;
    const int rl1  = m0 + quad;      // local rows
    const int rl2  = rl1 + 8;

    // add bias into acc
    #pragma unroll
    for (int t = 0; t < 16; t++) {
        const int c0 = t * 8 + qid * 2;
        float b0 = *reinterpret_cast<float*>(smem + S_BIAS + c0 * 4);
        float b1 = *reinterpret_cast<float*>(smem + S_BIAS + (c0 + 1) * 4);
        acc[t][0] += b0; acc[t][1] += b1;
        acc[t][2] += b0; acc[t][3] += b1;
    }
    // mean
    float s1 = 0.f, s2 = 0.f;
    #pragma unroll
    for (int t = 0; t < 16; t++) { s1 += acc[t][0] + acc[t][1]; s2 += acc[t][2] + acc[t][3]; }
    s1 += __shfl_xor_sync(0xffffffffu, s1, 1);
    s1 += __shfl_xor_sync(0xffffffffu, s1, 2);
    s2 += __shfl_xor_sync(0xffffffffu, s2, 1);
    s2 += __shfl_xor_sync(0xffffffffu, s2, 2);
    const float mu1 = s1 * (1.0f / 128.0f), mu2 = s2 * (1.0f / 128.0f);
    // variance
    float q1 = 0.f, q2 = 0.f;
    #pragma unroll
    for (int t = 0; t < 16; t++) {
        float d0 = acc[t][0] - mu1, d1 = acc[t][1] - mu1;
        float d2 = acc[t][2] - mu2, d3 = acc[t][3] - mu2;
        q1 += d0 * d0 + d1 * d1;
        q2 += d2 * d2 + d3 * d3;
    }
    q1 += __shfl_xor_sync(0xffffffffu, q1, 1);
    q1 += __shfl_xor_sync(0xffffffffu, q1, 2);
    q2 += __shfl_xor_sync(0xffffffffu, q2, 1);
    q2 += __shfl_xor_sync(0xffffffffu, q2, 2);
    const float inv1 = rsqrtf(q1 * (1.0f / 128.0f) + 1e-5f);
    const float inv2 = rsqrtf(q2 * (1.0f / 128.0f) + 1e-5f);

    const bool v1 = rl1 < nval, v2 = rl2 < nval;
    float* o1 = out + (size_t)(tile0 + rl1) * F;
    float* o2 = out + (size_t)(tile0 + rl2) * F;
    #pragma unroll
    for (int t = 0; t < 16; t++) {
        const int c0 = t * 8 + qid * 2;
        float g0 = *reinterpret_cast<float*>(smem + S_GAM + c0 * 4);
        float g1 = *reinterpret_cast<float*>(smem + S_GAM + (c0 + 1) * 4);
        float e0 = *reinterpret_cast<float*>(smem + S_BET + c0 * 4);
        float e1 = *reinterpret_cast<float*>(smem + S_BET + (c0 + 1) * 4);
        if (v1) {
            float2 r;
            r.x = fmaxf((acc[t][0] - mu1) * inv1 * g0 + e0, 0.0f);
            r.y = fmaxf((acc[t][1] - mu1) * inv1 * g1 + e1, 0.0f);
            *reinterpret_cast<float2*>(o1 + c0) = r;
        }
        if (v2) {
            float2 r;
            r.x = fmaxf((acc[t][2] - mu2) * inv2 * g0 + e0, 0.0f);
            r.y = fmaxf((acc[t][3] - mu2) * inv2 * g1 + e1, 0.0f);
            *reinterpret_cast<float2*>(o2 + c0) = r;
        }
    }
}

// ---------------- launch -----------------------------------------------------------
extern "C" void kernel_launch(void* const* d_in, const int* in_sizes, int n_in,
                              void* d_out, int out_size) {
    const float* h     = (const float*)d_in[0];
    const int*   src   = (const int*)  d_in[1];
    const int*   dst   = (const int*)  d_in[2];
    const float* W     = (const float*)d_in[3];
    const float* bias  = (const float*)d_in[4];
    const float* gamma = (const float*)d_in[5];
    const float* beta  = (const float*)d_in[6];
    float* out = (float*)d_out;

    const int N = in_sizes[0] / F;
    const int E = in_sizes[1];

    void* cnt_ptr = nullptr;
    cudaGetSymbolAddress(&cnt_ptr, g_cnt);
    cudaMemsetAsync(cnt_ptr, 0, (size_t)N * sizeof(int));

    wsplit<<<F, 64>>>(W);
    hist_dst<<<(E + 255) / 256, 256>>>(dst, E);

    int nb = (N + SCAN_CHUNK - 1) / SCAN_CHUNK;
    scan_part1<<<nb, 256>>>(N);
    scan_part2<<<1, 128>>>(nb);
    scan_part3<<<nb, 256>>>(N);
    fill_csr<<<(E + 255) / 256, 256>>>(src, dst, E);

    static int smem_set = 0;
    if (!smem_set) {
        cudaFuncSetAttribute(fused_gemm, cudaFuncAttributeMaxDynamicSharedMemorySize,
                             S_END);
        smem_set = 1;
    }
    int tiles = (N + MT - 1) / MT;
    fused_gemm<<<tiles, 256, S_END>>>(h, bias, gamma, beta, out, N);
}

// round 8
// speedup vs baseline: 2.2022x; 1.6029x over previous
#include <cuda_runtime.h>
#include <cuda_bf16.h>
#include <cstdint>
#include <cstddef>

#define NMAX 100000
#define EMAX 1600000
#define F    128
#define K2   256
#define MT   128            // nodes per GEMM tile
#define SCAN_CHUNK 1024
#define NBLK_SCAN  ((NMAX + SCAN_CHUNK - 1) / SCAN_CHUNK)

// x smem: [128 rows][264 bf16]  (528 B/row)
#define XSTR 264
// W smem: [128 cols][136 bf16]  (272 B/row)
#define WSTR 136

// smem byte offsets
#define S_BIAS 0
#define S_GAM  512
#define S_BET  1024
#define S_XH   2048
#define S_XL   (S_XH + 128 * XSTR * 2)          // 69632
#define S_WH   (S_XL + 128 * XSTR * 2)          // 137216
#define S_WL   (S_WH + 128 * WSTR * 2)          // 172032
#define S_END  (S_WL + 128 * WSTR * 2)          // 206848

// ---------------- scratch ------------------------------------------------------
__device__ int g_cnt[NMAX];
__device__ int g_off[NMAX];
__device__ int g_cur[NMAX];
__device__ int g_csr[EMAX];
__device__ unsigned long long g_wh[128 * 64];   // W bf16 hi [col][256] as u64x64
__device__ unsigned long long g_wl[128 * 64];   // W bf16 lo
// aggregated ah, bf16-split, row-major [node][128] (padded for tile overread)
__device__ unsigned long long g_ahh[(NMAX + MT) * 32];
__device__ unsigned long long g_ahl[(NMAX + MT) * 32];
__device__ int g_bsum[NBLK_SCAN];
__device__ int g_bbase[NBLK_SCAN];

// ---------------- helpers ------------------------------------------------------
__device__ __forceinline__ uint32_t smem_u32(const void* p) {
    uint32_t a;
    asm("{ .reg .u64 t; cvta.to.shared.u64 t, %1; cvt.u32.u64 %0, t; }" : "=r"(a) : "l"(p));
    return a;
}
__device__ __forceinline__ unsigned long long pk4(__nv_bfloat16 a, __nv_bfloat16 b,
                                                  __nv_bfloat16 c, __nv_bfloat16 d) {
    unsigned short u0 = __bfloat16_as_ushort(a), u1 = __bfloat16_as_ushort(b);
    unsigned short u2 = __bfloat16_as_ushort(c), u3 = __bfloat16_as_ushort(d);
    return (unsigned long long)u0 | ((unsigned long long)u1 << 16)
         | ((unsigned long long)u2 << 32) | ((unsigned long long)u3 << 48);
}
__device__ __forceinline__ void split4(float4 v, unsigned long long& hi,
                                       unsigned long long& lo) {
    __nv_bfloat16 hx = __float2bfloat16_rn(v.x), hy = __float2bfloat16_rn(v.y);
    __nv_bfloat16 hz = __float2bfloat16_rn(v.z), hw = __float2bfloat16_rn(v.w);
    __nv_bfloat16 lx = __float2bfloat16_rn(v.x - __bfloat162float(hx));
    __nv_bfloat16 ly = __float2bfloat16_rn(v.y - __bfloat162float(hy));
    __nv_bfloat16 lz = __float2bfloat16_rn(v.z - __bfloat162float(hz));
    __nv_bfloat16 lw = __float2bfloat16_rn(v.w - __bfloat162float(hw));
    hi = pk4(hx, hy, hz, hw);
    lo = pk4(lx, ly, lz, lw);
}
__device__ __forceinline__ void ldsm_x4(uint32_t* r, uint32_t addr) {
    asm volatile("ldmatrix.sync.aligned.m8n8.x4.shared.b16 {%0,%1,%2,%3}, [%4];"
                 : "=r"(r[0]), "=r"(r[1]), "=r"(r[2]), "=r"(r[3]) : "r"(addr));
}
__device__ __forceinline__ void ldsm_x2(uint32_t* r, uint32_t addr) {
    asm volatile("ldmatrix.sync.aligned.m8n8.x2.shared.b16 {%0,%1}, [%2];"
                 : "=r"(r[0]), "=r"(r[1]) : "r"(addr));
}
__device__ __forceinline__ void mma_bf16(float* d, const uint32_t* a, const uint32_t* b) {
    asm volatile("mma.sync.aligned.m16n8k16.row.col.f32.bf16.bf16.f32 "
                 "{%0,%1,%2,%3}, {%4,%5,%6,%7}, {%8,%9}, {%0,%1,%2,%3};"
                 : "+f"(d[0]), "+f"(d[1]), "+f"(d[2]), "+f"(d[3])
                 : "r"(a[0]), "r"(a[1]), "r"(a[2]), "r"(a[3]), "r"(b[0]), "r"(b[1]));
}
__device__ __forceinline__ void cp16(uint32_t saddr, const void* gptr) {
    asm volatile("cp.async.cg.shared.global [%0], [%1], 16;"
                 :: "r"(saddr), "l"(gptr) : "memory");
}
__device__ __forceinline__ void cp_commit_wait_all() {
    asm volatile("cp.async.commit_group;\n cp.async.wait_group 0;" ::: "memory");
}

// ---------------- prep: split W into bf16 hi/lo [col][256] -----------------------
__global__ void wsplit(const float* __restrict__ W) {
    int j  = blockIdx.x;          // output col 0..127
    int f4 = threadIdx.x;         // 0..63  (k group of 4)
    float4 v = *reinterpret_cast<const float4*>(W + (size_t)j * K2 + f4 * 4);
    unsigned long long hi, lo;
    split4(v, hi, lo);
    g_wh[j * 64 + f4] = hi;
    g_wl[j * 64 + f4] = lo;
}

// ---------------- prep: histogram / scan / fill ----------------------------------
__global__ void hist_dst(const int* __restrict__ dst, int E) {
    int i = blockIdx.x * blockDim.x + threadIdx.x;
    if (i < E) atomicAdd(&g_cnt[dst[i]], 1);
}
__global__ void scan_part1(int N) {
    const int b = blockIdx.x, tid = threadIdx.x;
    int i0 = b * SCAN_CHUNK + tid * 4;
    int s = 0;
    #pragma unroll
    for (int q = 0; q < 4; q++) { int i = i0 + q; if (i < N) s += g_cnt[i]; }
    #pragma unroll
    for (int o = 16; o > 0; o >>= 1) s += __shfl_xor_sync(0xffffffffu, s, o);
    __shared__ int ws[8];
    if ((tid & 31) == 0) ws[tid >> 5] = s;
    __syncthreads();
    if (tid == 0) {
        int t = 0;
        #pragma unroll
        for (int w = 0; w < 8; w++) t += ws[w];
        g_bsum[b] = t;
    }
}
__global__ void scan_part2(int nb) {
    const int tid = threadIdx.x, lane = tid & 31, wid = tid >> 5;
    int x = (tid < nb) ? g_bsum[tid] : 0;
    int inc = x;
    #pragma unroll
    for (int o = 1; o < 32; o <<= 1) {
        int t = __shfl_up_sync(0xffffffffu, inc, o);
        if (lane >= o) inc += t;
    }
    __shared__ int ws[4];
    if (lane == 31) ws[wid] = inc;
    __syncthreads();
    int wbase = 0;
    for (int w = 0; w < wid; w++) wbase += ws[w];
    if (tid < nb) g_bbase[tid] = wbase + inc - x;
}
__global__ void scan_part3(int N) {
    const int b = blockIdx.x, tid = threadIdx.x;
    const int lane = tid & 31, wid = tid >> 5;
    int i0 = b * SCAN_CHUNK + tid * 4;
    int v[4];
    #pragma unroll
    for (int q = 0; q < 4; q++) { int i = i0 + q; v[q] = (i < N) ? g_cnt[i] : 0; }
    int s = v[0] + v[1] + v[2] + v[3];
    int inc = s;
    #pragma unroll
    for (int o = 1; o < 32; o <<= 1) {
        int t = __shfl_up_sync(0xffffffffu, inc, o);
        if (lane >= o) inc += t;
    }
    __shared__ int ws[8], wse[8];
    if (lane == 31) ws[wid] = inc;
    __syncthreads();
    if (tid == 0) {
        int r = 0;
        #pragma unroll
        for (int w = 0; w < 8; w++) { wse[w] = r; r += ws[w]; }
    }
    __syncthreads();
    int run = g_bbase[b] + wse[wid] + (inc - s);
    #pragma unroll
    for (int q = 0; q < 4; q++) {
        int i = i0 + q;
        if (i < N) { g_off[i] = run; g_cur[i] = run; }
        run += v[q];
    }
}
__global__ void fill_csr(const int* __restrict__ src,
                         const int* __restrict__ dst, int E) {
    int i = blockIdx.x * blockDim.x + threadIdx.x;
    if (i < E) {
        int pos = atomicAdd(&g_cur[dst[i]], 1);
        g_csr[pos] = src[i];
    }
}

// ---------------- kernel A: high-occupancy gather-mean -> bf16-split ah ----------
// warp per node, lane covers 4 cols. No smem -> full occupancy, gather is BW-bound.
__global__ __launch_bounds__(256)
void aggregate(const float* __restrict__ h, int N) {
    const int n = blockIdx.x * 8 + (threadIdx.x >> 5);
    if (n >= N) return;
    const int lane = threadIdx.x & 31;
    const int j0 = lane * 4;
    const int beg = g_off[n];
    const int cnt = g_cnt[n];
    float4 a = make_float4(0.f, 0.f, 0.f, 0.f);
    int t = 0;
    for (; t + 4 <= cnt; t += 4) {
        int s0 = __ldg(g_csr + beg + t);
        int s1 = __ldg(g_csr + beg + t + 1);
        int s2 = __ldg(g_csr + beg + t + 2);
        int s3 = __ldg(g_csr + beg + t + 3);
        float4 v0 = *reinterpret_cast<const float4*>(h + (size_t)s0 * F + j0);
        float4 v1 = *reinterpret_cast<const float4*>(h + (size_t)s1 * F + j0);
        float4 v2 = *reinterpret_cast<const float4*>(h + (size_t)s2 * F + j0);
        float4 v3 = *reinterpret_cast<const float4*>(h + (size_t)s3 * F + j0);
        a.x += (v0.x + v1.x) + (v2.x + v3.x);
        a.y += (v0.y + v1.y) + (v2.y + v3.y);
        a.z += (v0.z + v1.z) + (v2.z + v3.z);
        a.w += (v0.w + v1.w) + (v2.w + v3.w);
    }
    for (; t < cnt; t++) {
        int s0 = __ldg(g_csr + beg + t);
        float4 v0 = *reinterpret_cast<const float4*>(h + (size_t)s0 * F + j0);
        a.x += v0.x; a.y += v0.y; a.z += v0.z; a.w += v0.w;
    }
    const float r = 1.0f / fmaxf((float)cnt, 1.0f);
    a.x *= r; a.y *= r; a.z *= r; a.w *= r;
    unsigned long long hi, lo;
    split4(a, hi, lo);
    g_ahh[(size_t)n * 32 + lane] = hi;
    g_ahl[(size_t)n * 32 + lane] = lo;
}

// ---------------- kernel B: staged GEMM (mma.sync) + LN + ReLU -------------------
__global__ __launch_bounds__(256, 1)
void fused_gemm(const float* __restrict__ h,
                const float* __restrict__ bias,
                const float* __restrict__ gamma,
                const float* __restrict__ beta,
                float* __restrict__ out,
                int N) {
    extern __shared__ char smem[];
    const uint32_t sb  = smem_u32(smem);
    const int tid  = threadIdx.x;
    const int lane = tid & 31;
    const int warp = tid >> 5;            // 0..7; warp owns rows m0..m0+15
    const int m0   = warp * 16;
    const int tile0 = blockIdx.x * MT;
    const int nval  = min(MT, N - tile0);

    // ---- cp.async: W chunk0 (hi+lo) and ah chunk (hi+lo). 32 x 16B per thread ----
    {
        const char* whs = reinterpret_cast<const char*>(g_wh);
        const char* wls = reinterpret_cast<const char*>(g_wl);
        #pragma unroll
        for (int it = 0; it < 8; it++) {
            int i = it * 256 + tid;            // 2048 each
            int col = i >> 4, q = i & 15;
            cp16(sb + S_WH + col * (WSTR * 2) + q * 16, whs + col * 512 + q * 16);
            cp16(sb + S_WL + col * (WSTR * 2) + q * 16, wls + col * 512 + q * 16);
        }
        const char* ahs = reinterpret_cast<const char*>(g_ahh + (size_t)tile0 * 32);
        const char* als = reinterpret_cast<const char*>(g_ahl + (size_t)tile0 * 32);
        #pragma unroll
        for (int it = 0; it < 8; it++) {
            int i = it * 256 + tid;            // 2048 each (128 rows x 16)
            int row = i >> 4, q = i & 15;
            cp16(sb + S_XH + row * (XSTR * 2) + F * 2 + q * 16, ahs + row * 256 + q * 16);
            cp16(sb + S_XL + row * (XSTR * 2) + F * 2 + q * 16, als + row * 256 + q * 16);
        }
    }

    // params (regular loads, overlap with cp.async)
    if (tid < F) {
        *reinterpret_cast<float*>(smem + S_BIAS + tid * 4) = bias[tid];
        *reinterpret_cast<float*>(smem + S_GAM  + tid * 4) = gamma[tid];
        *reinterpret_cast<float*>(smem + S_BET  + tid * 4) = beta[tid];
    }

    // ---- stage x (k 0..127) from h, bf16 split (overlaps with cp.async) ----
    #pragma unroll
    for (int it = 0; it < 16; it++) {
        int idx = it * 256 + tid;          // 4096 float4 slots
        int row = idx >> 5;
        int c   = idx & 31;                // float4 idx -> k0 = 4c
        float4 v = make_float4(0.f, 0.f, 0.f, 0.f);
        if (row < nval)
            v = *reinterpret_cast<const float4*>(h + (size_t)(tile0 + row) * F + c * 4);
        unsigned long long hi, lo;
        split4(v, hi, lo);
        *reinterpret_cast<unsigned long long*>(smem + S_XH + row * (XSTR * 2) + c * 8) = hi;
        *reinterpret_cast<unsigned long long*>(smem + S_XL + row * (XSTR * 2) + c * 8) = lo;
    }

    cp_commit_wait_all();
    __syncthreads();

    // ---- GEMM via mma.sync, 3-term bf16 split, fp32 accum ----
    float acc[16][4];
    #pragma unroll
    for (int t = 0; t < 16; t++)
        #pragma unroll
        for (int c = 0; c < 4; c++) acc[t][c] = 0.f;

    const int agrp = lane >> 3, ar = lane & 7;
    const int arow = m0 + ar + ((agrp & 1) ? 8 : 0);
    const int akof = (agrp & 2) ? 8 : 0;
    const uint32_t a_off = (uint32_t)arow * (XSTR * 2) + akof * 2;
    const int l15 = lane & 15;
    const uint32_t b_off = (uint32_t)(l15 & 7) * (WSTR * 2) + ((l15 >> 3) ? 16 : 0);

    #pragma unroll
    for (int ch = 0; ch < 2; ch++) {
        if (ch == 1) {
            __syncthreads();   // all warps done reading W chunk 0
            const char* whs = reinterpret_cast<const char*>(g_wh);
            const char* wls = reinterpret_cast<const char*>(g_wl);
            #pragma unroll
            for (int it = 0; it < 8; it++) {
                int i = it * 256 + tid;
                int col = i >> 4, q = i & 15;
                cp16(sb + S_WH + col * (WSTR * 2) + q * 16, whs + col * 512 + 256 + q * 16);
                cp16(sb + S_WL + col * (WSTR * 2) + q * 16, wls + col * 512 + 256 + q * 16);
            }
            cp_commit_wait_all();
            __syncthreads();
        }
        #pragma unroll
        for (int s = 0; s < 8; s++) {
            const uint32_t kg = ch * 128 + s * 16;
            uint32_t ah4[4], al4[4];
            ldsm_x4(ah4, sb + S_XH + a_off + kg * 2);
            ldsm_x4(al4, sb + S_XL + a_off + kg * 2);
            #pragma unroll
            for (int t = 0; t < 16; t++) {
                const uint32_t bo = (uint32_t)t * 8 * (WSTR * 2) + b_off + s * 32;
                uint32_t bh[2], bl[2];
                ldsm_x2(bh, sb + S_WH + bo);
                mma_bf16(acc[t], ah4, bh);
                mma_bf16(acc[t], al4, bh);
                ldsm_x2(bl, sb + S_WL + bo);
                mma_bf16(acc[t], ah4, bl);
            }
        }
    }

    // ---- epilogue: bias + LN (quad reduction) + affine + ReLU + store ----
    const int quad = lane >> 2;
    const int qid  = lane & 3;
    const int rl1  = m0 + quad;
    const int rl2  = rl1 + 8;

    #pragma unroll
    for (int t = 0; t < 16; t++) {
        const int c0 = t * 8 + qid * 2;
        float b0 = *reinterpret_cast<float*>(smem + S_BIAS + c0 * 4);
        float b1 = *reinterpret_cast<float*>(smem + S_BIAS + (c0 + 1) * 4);
        acc[t][0] += b0; acc[t][1] += b1;
        acc[t][2] += b0; acc[t][3] += b1;
    }
    float s1 = 0.f, s2 = 0.f;
    #pragma unroll
    for (int t = 0; t < 16; t++) { s1 += acc[t][0] + acc[t][1]; s2 += acc[t][2] + acc[t][3]; }
    s1 += __shfl_xor_sync(0xffffffffu, s1, 1);
    s1 += __shfl_xor_sync(0xffffffffu, s1, 2);
    s2 += __shfl_xor_sync(0xffffffffu, s2, 1);
    s2 += __shfl_xor_sync(0xffffffffu, s2, 2);
    const float mu1 = s1 * (1.0f / 128.0f), mu2 = s2 * (1.0f / 128.0f);
    float q1 = 0.f, q2 = 0.f;
    #pragma unroll
    for (int t = 0; t < 16; t++) {
        float d0 = acc[t][0] - mu1, d1 = acc[t][1] - mu1;
        float d2 = acc[t][2] - mu2, d3 = acc[t][3] - mu2;
        q1 += d0 * d0 + d1 * d1;
        q2 += d2 * d2 + d3 * d3;
    }
    q1 += __shfl_xor_sync(0xffffffffu, q1, 1);
    q1 += __shfl_xor_sync(0xffffffffu, q1, 2);
    q2 += __shfl_xor_sync(0xffffffffu, q2, 1);
    q2 += __shfl_xor_sync(0xffffffffu, q2, 2);
    const float inv1 = rsqrtf(q1 * (1.0f / 128.0f) + 1e-5f);
    const float inv2 = rsqrtf(q2 * (1.0f / 128.0f) + 1e-5f);

    const bool v1 = rl1 < nval, v2 = rl2 < nval;
    float* o1 = out + (size_t)(tile0 + rl1) * F;
    float* o2 = out + (size_t)(tile0 + rl2) * F;
    #pragma unroll
    for (int t = 0; t < 16; t++) {
        const int c0 = t * 8 + qid * 2;
        float g0 = *reinterpret_cast<float*>(smem + S_GAM + c0 * 4);
        float g1 = *reinterpret_cast<float*>(smem + S_GAM + (c0 + 1) * 4);
        float e0 = *reinterpret_cast<float*>(smem + S_BET + c0 * 4);
        float e1 = *reinterpret_cast<float*>(smem + S_BET + (c0 + 1) * 4);
        if (v1) {
            float2 r;
            r.x = fmaxf((acc[t][0] - mu1) * inv1 * g0 + e0, 0.0f);
            r.y = fmaxf((acc[t][1] - mu1) * inv1 * g1 + e1, 0.0f);
            *reinterpret_cast<float2*>(o1 + c0) = r;
        }
        if (v2) {
            float2 r;
            r.x = fmaxf((acc[t][2] - mu2) * inv2 * g0 + e0, 0.0f);
            r.y = fmaxf((acc[t][3] - mu2) * inv2 * g1 + e1, 0.0f);
            *reinterpret_cast<float2*>(o2 + c0) = r;
        }
    }
}

// ---------------- launch -----------------------------------------------------------
extern "C" void kernel_launch(void* const* d_in, const int* in_sizes, int n_in,
                              void* d_out, int out_size) {
    const float* h     = (const float*)d_in[0];
    const int*   src   = (const int*)  d_in[1];
    const int*   dst   = (const int*)  d_in[2];
    const float* W     = (const float*)d_in[3];
    const float* bias  = (const float*)d_in[4];
    const float* gamma = (const float*)d_in[5];
    const float* beta  = (const float*)d_in[6];
    float* out = (float*)d_out;

    const int N = in_sizes[0] / F;
    const int E = in_sizes[1];

    void* cnt_ptr = nullptr;
    cudaGetSymbolAddress(&cnt_ptr, g_cnt);
    cudaMemsetAsync(cnt_ptr, 0, (size_t)N * sizeof(int));

    wsplit<<<F, 64>>>(W);
    hist_dst<<<(E + 255) / 256, 256>>>(dst, E);

    int nb = (N + SCAN_CHUNK - 1) / SCAN_CHUNK;
    scan_part1<<<nb, 256>>>(N);
    scan_part2<<<1, 128>>>(nb);
    scan_part3<<<nb, 256>>>(N);
    fill_csr<<<(E + 255) / 256, 256>>>(src, dst, E);

    aggregate<<<(N + 7) / 8, 256>>>(h, N);

    static int smem_set = 0;
    if (!smem_set) {
        cudaFuncSetAttribute(fused_gemm, cudaFuncAttributeMaxDynamicSharedMemorySize,
                             S_END);
        smem_set = 1;
    }
    int tiles = (N + MT - 1) / MT;
    fused_gemm<<<tiles, 256, S_END>>>(h, bias, gamma, beta, out, N);
}